// round 1
// baseline (speedup 1.0000x reference)
#include <cuda_runtime.h>

#define N_TOT 6016

// Static shape tables: sizes g = 256 + 16*g, g in [0,16)
__constant__ int c_node_start[17] = {
    0,256,528,816,1120,1440,1776,2128,2496,2880,3280,3696,4128,4576,5040,5520,6016};
__constant__ long long c_pair_start[17] = {
    0,65536,139520,222464,314880,417280,530176,654080,789504,936960,
    1096960,1270016,1456640,1657344,1872640,2103040,2349056};
__constant__ int c_tile_start[17] = {
    0,256,545,869,1230,1630,2071,2555,3084,3660,4285,4961,5690,6474,7315,8215,9176};

// staged per-node MLP output t[N_TOT][32]
__device__ float g_t[N_TOT * 32];

// ---------------------------------------------------------------------------
// Kernel 1: per-node MLP  t = relu(ape @ W1 + b1) @ W2 + b2
// ---------------------------------------------------------------------------
__global__ __launch_bounds__(128)
void mlp_kernel(const float* __restrict__ ape,
                const float* __restrict__ W1, const float* __restrict__ b1,
                const float* __restrict__ W2, const float* __restrict__ b2) {
    __shared__ float sW1[16 * 64];
    __shared__ float sW2[64 * 32];
    __shared__ float sb1[64];
    __shared__ float sb2[32];
    int tid = threadIdx.x;
    for (int k = tid; k < 16 * 64; k += 128) sW1[k] = W1[k];
    for (int k = tid; k < 64 * 32; k += 128) sW2[k] = W2[k];
    if (tid < 64) sb1[tid] = b1[tid];
    if (tid < 32) sb2[tid] = b2[tid];
    __syncthreads();

    int n = blockIdx.x * 128 + tid;
    if (n >= N_TOT) return;

    float a[16];
    const float4* ap = (const float4*)(ape + n * 16);
    float4 a0 = ap[0], a1 = ap[1], a2 = ap[2], a3 = ap[3];
    a[0]=a0.x; a[1]=a0.y; a[2]=a0.z; a[3]=a0.w;
    a[4]=a1.x; a[5]=a1.y; a[6]=a1.z; a[7]=a1.w;
    a[8]=a2.x; a[9]=a2.y; a[10]=a2.z; a[11]=a2.w;
    a[12]=a3.x; a[13]=a3.y; a[14]=a3.z; a[15]=a3.w;

    float o[32];
#pragma unroll
    for (int c = 0; c < 32; c++) o[c] = sb2[c];

#pragma unroll 4
    for (int h = 0; h < 64; h++) {
        float v = sb1[h];
#pragma unroll
        for (int k = 0; k < 16; k++) v = fmaf(a[k], sW1[k * 64 + h], v);
        v = fmaxf(v, 0.0f);
#pragma unroll
        for (int c = 0; c < 32; c++) o[c] = fmaf(v, sW2[h * 32 + c], o[c]);
    }

    float4* tp = (float4*)(g_t + n * 32);
#pragma unroll
    for (int q = 0; q < 8; q++) {
        float4 v;
        v.x = o[q * 4 + 0]; v.y = o[q * 4 + 1];
        v.z = o[q * 4 + 2]; v.w = o[q * 4 + 3];
        tp[q] = v;
    }
}

// ---------------------------------------------------------------------------
// Kernel 2: pair expansion. One block per 16x16 (i,j) tile of one graph.
// out[pair_start[b] + i*n_b + j][:] = t[start_b+i][:] + t[start_b+j][:]
// All n_b are multiples of 16 -> all tiles full, no bounds checks.
// ---------------------------------------------------------------------------
__global__ __launch_bounds__(256)
void pair_kernel(float* __restrict__ out) {
    int blk = blockIdx.x;

    // find graph b (uniform across block; 15 predicated compares)
    int b = 0;
#pragma unroll
    for (int g = 1; g < 16; g++)
        if (blk >= c_tile_start[g]) b = g;

    int lt  = blk - c_tile_start[b];
    int tpr = 16 + b;            // tiles per row = n_b/16
    int nb  = tpr << 4;          // n_b
    int ti  = lt / tpr;
    int tj  = lt - ti * tpr;
    int ns  = c_node_start[b];
    long long ps = c_pair_start[b];

    __shared__ float4 s_ti[16 * 8];   // 16 i-rows x 8 float4
    __shared__ float4 s_tj[16 * 8];   // 16 j-rows x 8 float4

    const float4* tp = (const float4*)g_t;
    int tid = threadIdx.x;
    if (tid < 128) {
        s_ti[tid] = tp[(ns + ti * 16) * 8 + tid];
    } else {
        s_tj[tid - 128] = tp[(ns + tj * 16) * 8 + (tid - 128)];
    }
    __syncthreads();

    float4* op = (float4*)out;
    int l    = tid & 127;        // position within a 16-row (j) group: j*8+q
    int half = tid >> 7;         // 0 or 1: which ii this thread covers per step
    int q    = l & 7;

    float4 vj = s_tj[l];         // t[j-row], float4 q — reused for all 8 steps

    long long rowbase = ps + (long long)(ti * 16) * nb + tj * 16;

#pragma unroll
    for (int step = 0; step < 8; step++) {
        int ii = step * 2 + half;
        float4 vi = s_ti[ii * 8 + q];
        float4 v;
        v.x = vi.x + vj.x; v.y = vi.y + vj.y;
        v.z = vi.z + vj.z; v.w = vi.w + vj.w;
        // 128 threads write 128 consecutive float4 (2KB contiguous)
        op[(rowbase + (long long)ii * nb) * 8 + l] = v;
    }
}

// ---------------------------------------------------------------------------
extern "C" void kernel_launch(void* const* d_in, const int* in_sizes, int n_in,
                              void* d_out, int out_size) {
    const float* ape = (const float*)d_in[0];
    const float* W1  = (const float*)d_in[1];
    const float* b1  = (const float*)d_in[2];
    const float* W2  = (const float*)d_in[3];
    const float* b2  = (const float*)d_in[4];
    float* out = (float*)d_out;

    mlp_kernel<<<(N_TOT + 127) / 128, 128>>>(ape, W1, b1, W2, b2);
    pair_kernel<<<9176, 256>>>(out);
}

// round 2
// speedup vs baseline: 1.0676x; 1.0676x over previous
#include <cuda_runtime.h>

#define N_TOT 6016

// Static shape tables: sizes g = 256 + 16*g, g in [0,16)
__constant__ int c_node_start[17] = {
    0,256,528,816,1120,1440,1776,2128,2496,2880,3280,3696,4128,4576,5040,5520,6016};
__constant__ long long c_pair_start[17] = {
    0,65536,139520,222464,314880,417280,530176,654080,789504,936960,
    1096960,1270016,1456640,1657344,1872640,2103040,2349056};
__constant__ int c_tile_start[17] = {
    0,256,545,869,1230,1630,2071,2555,3084,3660,4285,4961,5690,6474,7315,8215,9176};

// staged per-node MLP output t[N_TOT][32]
__device__ float g_t[N_TOT * 32];

// ---------------------------------------------------------------------------
// Kernel 1: per-node MLP  t = relu(ape @ W1 + b1) @ W2 + b2
// 4 threads per node; each computes all 64 hidden values (vectorized LDS.128
// weight loads) but only 8 of the 32 outputs.
// ---------------------------------------------------------------------------
__global__ __launch_bounds__(256)
void mlp_kernel(const float* __restrict__ ape,
                const float* __restrict__ W1, const float* __restrict__ b1,
                const float* __restrict__ W2, const float* __restrict__ b2) {
    __shared__ float sW1t[64 * 16];   // transposed: sW1t[h*16+k] = W1[k*64+h]
    __shared__ float sW2[64 * 32];
    __shared__ float sb1[64];
    __shared__ float sb2[32];
    int tid = threadIdx.x;

    for (int idx = tid; idx < 64 * 16; idx += 256) {
        int h = idx >> 4, k = idx & 15;
        sW1t[idx] = W1[k * 64 + h];
    }
    for (int idx = tid; idx < 64 * 32; idx += 256) sW2[idx] = W2[idx];
    if (tid < 64) sb1[tid] = b1[tid];
    if (tid < 32) sb2[tid] = b2[tid];
    __syncthreads();

    int n  = blockIdx.x * 64 + (tid >> 2);
    int c0 = (tid & 3) * 8;
    if (n >= N_TOT) return;

    float a[16];
    const float4* ap = (const float4*)(ape + n * 16);
    float4 a0 = ap[0], a1 = ap[1], a2 = ap[2], a3 = ap[3];
    a[0]=a0.x; a[1]=a0.y; a[2]=a0.z; a[3]=a0.w;
    a[4]=a1.x; a[5]=a1.y; a[6]=a1.z; a[7]=a1.w;
    a[8]=a2.x; a[9]=a2.y; a[10]=a2.z; a[11]=a2.w;
    a[12]=a3.x; a[13]=a3.y; a[14]=a3.z; a[15]=a3.w;

    float o[8];
#pragma unroll
    for (int c = 0; c < 8; c++) o[c] = sb2[c0 + c];

    const float4* w1v = (const float4*)sW1t;
    const float4* w2v = (const float4*)(sW2 + c0);

#pragma unroll 8
    for (int h = 0; h < 64; h++) {
        float4 w0 = w1v[h * 4 + 0], w1_ = w1v[h * 4 + 1];
        float4 w2_ = w1v[h * 4 + 2], w3 = w1v[h * 4 + 3];
        float v = sb1[h];
        v = fmaf(a[0],  w0.x, v); v = fmaf(a[1],  w0.y, v);
        v = fmaf(a[2],  w0.z, v); v = fmaf(a[3],  w0.w, v);
        v = fmaf(a[4],  w1_.x, v); v = fmaf(a[5],  w1_.y, v);
        v = fmaf(a[6],  w1_.z, v); v = fmaf(a[7],  w1_.w, v);
        v = fmaf(a[8],  w2_.x, v); v = fmaf(a[9],  w2_.y, v);
        v = fmaf(a[10], w2_.z, v); v = fmaf(a[11], w2_.w, v);
        v = fmaf(a[12], w3.x, v); v = fmaf(a[13], w3.y, v);
        v = fmaf(a[14], w3.z, v); v = fmaf(a[15], w3.w, v);
        v = fmaxf(v, 0.0f);
        float4 u0 = w2v[h * 8 + 0];     // sW2[h*32 + c0 .. c0+3]
        float4 u1 = w2v[h * 8 + 1];     // sW2[h*32 + c0+4 .. c0+7]
        o[0] = fmaf(v, u0.x, o[0]); o[1] = fmaf(v, u0.y, o[1]);
        o[2] = fmaf(v, u0.z, o[2]); o[3] = fmaf(v, u0.w, o[3]);
        o[4] = fmaf(v, u1.x, o[4]); o[5] = fmaf(v, u1.y, o[5]);
        o[6] = fmaf(v, u1.z, o[6]); o[7] = fmaf(v, u1.w, o[7]);
    }

    float4* tp = (float4*)(g_t + n * 32 + c0);
    float4 r0, r1;
    r0.x = o[0]; r0.y = o[1]; r0.z = o[2]; r0.w = o[3];
    r1.x = o[4]; r1.y = o[5]; r1.z = o[6]; r1.w = o[7];
    tp[0] = r0;
    tp[1] = r1;
}

// ---------------------------------------------------------------------------
// Kernel 2: pair expansion. One block per 16x16 (i,j) tile of one graph.
// out[pair_start[b] + i*n_b + j][:] = t[start_b+i][:] + t[start_b+j][:]
// All n_b are multiples of 16 -> all tiles full, no bounds checks.
// ---------------------------------------------------------------------------
__global__ __launch_bounds__(256)
void pair_kernel(float* __restrict__ out) {
    int blk = blockIdx.x;

    // find graph b (uniform across block; 15 predicated compares)
    int b = 0;
#pragma unroll
    for (int g = 1; g < 16; g++)
        if (blk >= c_tile_start[g]) b = g;

    int lt  = blk - c_tile_start[b];
    int tpr = 16 + b;            // tiles per row = n_b/16
    int nb  = tpr << 4;          // n_b
    int ti  = lt / tpr;
    int tj  = lt - ti * tpr;
    int ns  = c_node_start[b];
    long long ps = c_pair_start[b];

    __shared__ float4 s_ti[16 * 8];   // 16 i-rows x 8 float4
    __shared__ float4 s_tj[16 * 8];   // 16 j-rows x 8 float4

    const float4* tp = (const float4*)g_t;
    int tid = threadIdx.x;
    if (tid < 128) {
        s_ti[tid] = tp[(ns + ti * 16) * 8 + tid];
    } else {
        s_tj[tid - 128] = tp[(ns + tj * 16) * 8 + (tid - 128)];
    }
    __syncthreads();

    int l    = tid & 127;        // position within a 16-row (j) group: j*8+q
    int half = tid >> 7;         // 0 or 1: which ii this thread covers per step
    int q    = l & 7;

    float4 vj = s_tj[l];         // t[j-row], float4 q — reused for all 8 steps

    // store pointer: rows ii = step*2 + half; stride between steps = 2*nb rows
    float4* op = (float4*)out
               + (ps + (long long)(ti * 16 + half) * nb + tj * 16) * 8 + l;
    long long stride = (long long)nb * 16;   // 2 rows of nb float4-pairs: 2*nb*8

    const float4* sip = s_ti + half * 8 + q;

#pragma unroll
    for (int step = 0; step < 8; step++) {
        float4 vi = sip[step * 16];
        float4 v;
        v.x = vi.x + vj.x; v.y = vi.y + vj.y;
        v.z = vi.z + vj.z; v.w = vi.w + vj.w;
        op[step * stride] = v;   // 128 threads -> 2KB contiguous wavefront
    }
}

// ---------------------------------------------------------------------------
extern "C" void kernel_launch(void* const* d_in, const int* in_sizes, int n_in,
                              void* d_out, int out_size) {
    const float* ape = (const float*)d_in[0];
    const float* W1  = (const float*)d_in[1];
    const float* b1  = (const float*)d_in[2];
    const float* W2  = (const float*)d_in[3];
    const float* b2  = (const float*)d_in[4];
    float* out = (float*)d_out;

    mlp_kernel<<<94, 256>>>(ape, W1, b1, W2, b2);
    pair_kernel<<<9176, 256>>>(out);
}